// round 3
// baseline (speedup 1.0000x reference)
#include <cuda_runtime.h>
#include <cuda_bf16.h>
#include <stdint.h>

#define I_FEAT 4096
#define O_FEAT 11008
#define N_ROWS 4096
#define NBLK   16        // 256-elem blocks per row
#define KP     8192      // interleaved K' = 2 * I_FEAT (Xh/Xl sub-blocks of 256)
#define NSB    32        // sub-blocks
#define BM     128
#define BN     128

// ---------------- scratch (allocation-free device globals) ----------------
__device__ int8_t g_Xq[(size_t)N_ROWS * KP];      // interleaved Xh/Xl, row stride 8192
__device__ int8_t g_q[(size_t)O_FEAT * I_FEAT];   // idx - 128
__device__ float  g_xsum[(size_t)N_ROWS * NBLK];  // exact per-block sums of x
__device__ float  g_rs[N_ROWS];                   // per-row quant unit

// ---------------- quantize x: per-row 15-bit split int8 ----------------
__global__ void __launch_bounds__(256) quant_x_kernel(const float* __restrict__ x) {
    const int row = blockIdx.x, t = threadIdx.x;
    const float4* xp = reinterpret_cast<const float4*>(x + (size_t)row * I_FEAT + t * 16);
    float vals[16];
#pragma unroll
    for (int g = 0; g < 4; ++g) {
        float4 v = xp[g];
        vals[g * 4 + 0] = v.x; vals[g * 4 + 1] = v.y;
        vals[g * 4 + 2] = v.z; vals[g * 4 + 3] = v.w;
    }
    float mx = 0.0f, sum = 0.0f;
#pragma unroll
    for (int i = 0; i < 16; ++i) { mx = fmaxf(mx, fabsf(vals[i])); sum += vals[i]; }
#pragma unroll
    for (int o = 16; o; o >>= 1) mx = fmaxf(mx, __shfl_xor_sync(~0u, mx, o));
    __shared__ float smax[8];
    if ((t & 31) == 0) smax[t >> 5] = mx;
    __syncthreads();
    mx = smax[0];
#pragma unroll
    for (int i = 1; i < 8; ++i) mx = fmaxf(mx, smax[i]);
    const float inv = mx > 0.0f ? 16256.0f / mx : 0.0f;

    uint32_t hw[4] = {0, 0, 0, 0}, lw[4] = {0, 0, 0, 0};
#pragma unroll
    for (int g = 0; g < 4; ++g)
#pragma unroll
        for (int j = 0; j < 4; ++j) {
            int vi = __float2int_rn(vals[g * 4 + j] * inv);
            int xh = (vi + 64) >> 7;
            int xl = vi - (xh << 7);
            hw[g] |= (uint32_t)(xh & 255) << (8 * j);
            lw[g] |= (uint32_t)(xl & 255) << (8 * j);
        }
    const size_t base = (size_t)row * KP + (size_t)(t >> 4) * 512 + (t & 15) * 16;
    *reinterpret_cast<uint4*>(g_Xq + base)       = make_uint4(hw[0], hw[1], hw[2], hw[3]);
    *reinterpret_cast<uint4*>(g_Xq + base + 256) = make_uint4(lw[0], lw[1], lw[2], lw[3]);

#pragma unroll
    for (int o = 8; o; o >>= 1) sum += __shfl_down_sync(~0u, sum, o, 16);
    if ((t & 15) == 0) g_xsum[row * NBLK + (t >> 4)] = sum;
    if (t == 0) g_rs[row] = mx * (1.0f / 16256.0f);
}

// ---------------- pack idx -> int8 (idx - 128, exact) ----------------
__global__ void __launch_bounds__(256) pack_q_kernel(const int* __restrict__ idx) {
    const size_t i4 = ((size_t)blockIdx.x * 256 + threadIdx.x) * 4;
    int4 q = *reinterpret_cast<const int4*>(idx + i4);
    uint32_t w = (uint32_t)((q.x - 128) & 255)
               | (uint32_t)((q.y - 128) & 255) << 8
               | (uint32_t)((q.z - 128) & 255) << 16
               | (uint32_t)((q.w - 128) & 255) << 24;
    *reinterpret_cast<uint32_t*>(g_q + i4) = w;
}

// ---------------- GEMM helpers ----------------
__device__ __forceinline__ void cp16(uint32_t dst, const void* src) {
    asm volatile("cp.async.cg.shared.global [%0], [%1], 16;\n" :: "r"(dst), "l"(src));
}
__device__ __forceinline__ void ldsm4(uint32_t& r0, uint32_t& r1, uint32_t& r2, uint32_t& r3,
                                      uint32_t addr) {
    asm volatile("ldmatrix.sync.aligned.m8n8.x4.shared.b16 {%0,%1,%2,%3}, [%4];\n"
        : "=r"(r0), "=r"(r1), "=r"(r2), "=r"(r3) : "r"(addr));
}
__device__ __forceinline__ void mma_s8(int* c, const uint32_t* a, const uint32_t* b) {
    asm volatile("mma.sync.aligned.m16n8k32.row.col.s32.s8.s8.s32 "
        "{%0,%1,%2,%3}, {%4,%5,%6,%7}, {%8,%9}, {%0,%1,%2,%3};\n"
        : "+r"(c[0]), "+r"(c[1]), "+r"(c[2]), "+r"(c[3])
        : "r"(a[0]), "r"(a[1]), "r"(a[2]), "r"(a[3]), "r"(b[0]), "r"(b[1]));
}

// smem layout (bytes from 1024-aligned base)
#define SX   0u         // X' stages: 2 x 32768
#define SQ   65536u     // q  stages: 2 x 32768
#define SF   131072u    // fold scales [32][128] f32
#define SXS  147456u    // xsum tile   [16][128] f32
#define SBB  155648u    // bias_ab     [16][128] f32
#define SBV  163840u    // bias        [128] f32
#define SRS  164352u    // row scale   [128] f32
#define SM_TOTAL (164864u + 1024u)

// ---------------- int8 split GEMM + affine epilogue ----------------
__global__ void __launch_bounds__(256, 1)
gemm_i8_kernel(const float* __restrict__ scales, const float* __restrict__ bab,
               const float* __restrict__ bias, float* __restrict__ out) {
    extern __shared__ __align__(16) char smraw[];
    char* smc = (char*)(((uintptr_t)smraw + 1023) & ~(uintptr_t)1023);
    const uint32_t smb = (uint32_t)__cvta_generic_to_shared(smc);

    const int tid = threadIdx.x;
    const int lane = tid & 31;
    const int wid = tid >> 5;
    const int wm = (wid & 1) * 64;        // 2 warps in m, warp tile 64x32
    const int wn = (wid >> 1) * 32;       // 4 warps in n
    const int m0 = (blockIdx.x & 31) * BM;      // m fastest: q tiles shared via L2
    const int n0 = (blockIdx.x >> 5) * BN;

    // ---- preload fold scales: sf[sb][c] = scales[(n0+c)*16 + sb/2] * {128,1}/127
    {
        float* sf = (float*)(smc + SF);
        for (int e = tid; e < 32 * 128; e += 256) {
            int sb = e >> 7, c = e & 127;
            float s = __ldg(scales + (size_t)(n0 + c) * NBLK + (sb >> 1));
            sf[e] = s * ((sb & 1) ? (1.0f / 127.0f) : (128.0f / 127.0f));
        }
    }

    // ---- cp.async descriptors: thread covers rows (tid>>4)+16i, chunk tid&15
    const int lrow = tid >> 4;
    const int lch = tid & 15;
    const uint32_t dst0 = (uint32_t)lrow * 256u
                        + (uint32_t)((lch & 7) ^ (lrow & 7)) * 16u
                        + (uint32_t)(lch >> 3) * 128u;

    auto load_x = [&](int sb) {
        uint32_t d = smb + SX + (uint32_t)(sb & 1) * 32768u + dst0;
        const int8_t* s = g_Xq + (size_t)(m0 + lrow) * KP + (size_t)sb * 256 + lch * 16;
#pragma unroll
        for (int i = 0; i < 8; ++i) { cp16(d, s); d += 4096u; s += (size_t)16 * KP; }
    };
    auto load_q = [&](int b) {
        uint32_t d = smb + SQ + (uint32_t)(b & 1) * 32768u + dst0;
        const int8_t* s = g_q + (size_t)(n0 + lrow) * I_FEAT + (size_t)b * 256 + lch * 16;
#pragma unroll
        for (int i = 0; i < 8; ++i) { cp16(d, s); d += 4096u; s += (size_t)16 * I_FEAT; }
    };

    float accF[4][4][4];
#pragma unroll
    for (int a = 0; a < 4; ++a)
#pragma unroll
        for (int b = 0; b < 4; ++b)
#pragma unroll
            for (int c = 0; c < 4; ++c) accF[a][b][c] = 0.0f;

    // prologue
    load_q(0);
    load_x(0);
    asm volatile("cp.async.commit_group;\n" ::: "memory");

    for (int sb = 0; sb < NSB; ++sb) {
        if (sb + 1 < NSB) {
            load_x(sb + 1);
            if (((sb + 1) & 1) == 0) load_q((sb + 1) >> 1);
            asm volatile("cp.async.commit_group;\n" ::: "memory");
            asm volatile("cp.async.wait_group 1;\n" ::: "memory");
        } else {
            asm volatile("cp.async.wait_group 0;\n" ::: "memory");
        }
        __syncthreads();

        int accI[4][4][4];
#pragma unroll
        for (int a = 0; a < 4; ++a)
#pragma unroll
            for (int b = 0; b < 4; ++b)
#pragma unroll
                for (int c = 0; c < 4; ++c) accI[a][b][c] = 0;

        const uint32_t xb = smb + SX + (uint32_t)(sb & 1) * 32768u;
        const uint32_t qb = smb + SQ + (uint32_t)((sb >> 1) & 1) * 32768u;

#pragma unroll
        for (int ks = 0; ks < 8; ++ks) {
            uint32_t a[4][4];
            {
                const int ci = ks * 2 + (lane >> 4);
#pragma unroll
                for (int mi = 0; mi < 4; ++mi) {
                    int r = wm + mi * 16 + (lane & 15);
                    uint32_t ad = xb + (uint32_t)r * 256u + (uint32_t)((ci >> 3) << 7)
                                + (uint32_t)(((ci & 7) ^ (r & 7)) << 4);
                    ldsm4(a[mi][0], a[mi][1], a[mi][2], a[mi][3], ad);
                }
            }
            uint32_t bf[4][2];
            {
                const int ci = ks * 2 + ((lane >> 3) & 1);
#pragma unroll
                for (int nj = 0; nj < 2; ++nj) {
                    int r = wn + nj * 16 + (lane & 7) + ((lane >> 4) << 3);
                    uint32_t ad = qb + (uint32_t)r * 256u + (uint32_t)((ci >> 3) << 7)
                                + (uint32_t)(((ci & 7) ^ (r & 7)) << 4);
                    ldsm4(bf[nj * 2][0], bf[nj * 2][1], bf[nj * 2 + 1][0], bf[nj * 2 + 1][1], ad);
                }
            }
#pragma unroll
            for (int mi = 0; mi < 4; ++mi)
#pragma unroll
                for (int ni = 0; ni < 4; ++ni)
                    mma_s8(accI[mi][ni], a[mi], bf[ni]);
        }

        // fold int block-partials into fp32 with per-(col, sub-block) scales
        const float* sf = (const float*)(smc + SF) + sb * 128;
#pragma unroll
        for (int ni = 0; ni < 4; ++ni) {
            const int c0 = wn + ni * 8 + (lane & 3) * 2;
            const float f0 = sf[c0], f1 = sf[c0 + 1];
#pragma unroll
            for (int mi = 0; mi < 4; ++mi) {
                accF[mi][ni][0] += __int2float_rn(accI[mi][ni][0]) * f0;
                accF[mi][ni][1] += __int2float_rn(accI[mi][ni][1]) * f1;
                accF[mi][ni][2] += __int2float_rn(accI[mi][ni][2]) * f0;
                accF[mi][ni][3] += __int2float_rn(accI[mi][ni][3]) * f1;
            }
        }
        __syncthreads();
    }

    // ---- epilogue: out = rs_row*accF + sum_b bab[c,b]*xsum[r,b] + bias[c]
    {
        float* xs = (float*)(smc + SXS);
        float* bb = (float*)(smc + SBB);
        float* bv = (float*)(smc + SBV);
        float* rs = (float*)(smc + SRS);
        for (int e = tid; e < 16 * 128; e += 256) {
            int b = e >> 7, r = e & 127;
            xs[e] = g_xsum[(size_t)(m0 + r) * NBLK + b];
        }
        for (int e = tid; e < 16 * 128; e += 256) {
            int b = e >> 7, c = e & 127;
            bb[e] = __ldg(bab + (size_t)(n0 + c) * NBLK + b);
        }
        if (tid < 128) { bv[tid] = __ldg(bias + n0 + tid); rs[tid] = g_rs[m0 + tid]; }
        __syncthreads();

#pragma unroll
        for (int mi = 0; mi < 4; ++mi) {
            const int r0 = wm + mi * 16 + (lane >> 2);
            float xr0[16], xr1[16];
#pragma unroll
            for (int b = 0; b < 16; ++b) {
                xr0[b] = xs[b * 128 + r0];
                xr1[b] = xs[b * 128 + r0 + 8];
            }
            const float s0 = rs[r0], s1 = rs[r0 + 8];
            float* o0 = out + (size_t)(m0 + r0) * O_FEAT + n0;
            float* o1 = out + (size_t)(m0 + r0 + 8) * O_FEAT + n0;
#pragma unroll
            for (int ni = 0; ni < 4; ++ni) {
                const int c0 = wn + ni * 8 + (lane & 3) * 2;
                float d00 = bv[c0], d01 = bv[c0 + 1], d10 = d00, d11 = d01;
#pragma unroll
                for (int b = 0; b < 16; ++b) {
                    const float w0 = bb[b * 128 + c0], w1 = bb[b * 128 + c0 + 1];
                    d00 += xr0[b] * w0; d01 += xr0[b] * w1;
                    d10 += xr1[b] * w0; d11 += xr1[b] * w1;
                }
                float2 v0 = { accF[mi][ni][0] * s0 + d00, accF[mi][ni][1] * s0 + d01 };
                float2 v1 = { accF[mi][ni][2] * s1 + d10, accF[mi][ni][3] * s1 + d11 };
                *reinterpret_cast<float2*>(o0 + c0) = v0;
                *reinterpret_cast<float2*>(o1 + c0) = v1;
            }
        }
    }
}

// ---------------- launch ----------------
extern "C" void kernel_launch(void* const* d_in, const int* in_sizes, int n_in,
                              void* d_out, int out_size) {
    const float* x    = (const float*)d_in[0];
    const int*   idx  = (const int*)d_in[1];
    const float* sc   = (const float*)d_in[2];
    const float* bab  = (const float*)d_in[3];
    const float* bias = (const float*)d_in[4];
    float* out = (float*)d_out;

    quant_x_kernel<<<N_ROWS, 256>>>(x);
    pack_q_kernel<<<(int)(((size_t)O_FEAT * I_FEAT) / 1024), 256>>>(idx);

    cudaFuncSetAttribute(gemm_i8_kernel, cudaFuncAttributeMaxDynamicSharedMemorySize,
                         (int)SM_TOTAL);
    const int grid = (N_ROWS / BM) * (O_FEAT / BN);   // 32 * 86 = 2752
    gemm_i8_kernel<<<grid, 256, SM_TOTAL>>>(sc, bab, bias, out);
}

// round 4
// speedup vs baseline: 3.7491x; 3.7491x over previous
#include <cuda_runtime.h>
#include <cuda_fp16.h>
#include <stdint.h>

#define I_FEAT 4096
#define O_FEAT 11008
#define N_ROWS 4096

#define BM 128
#define BN 256
#define BK 32
#define SSTRIDE 40                  // halves per smem row (32 + 8 pad) -> conflict-free ldmatrix
#define NKT (I_FEAT / BK)           // 128 k-tiles

// ---------------- scratch (allocation-free: device globals) ----------------
__device__ __half g_Wh[(size_t)O_FEAT * I_FEAT];   // dequantized W, fp16
__device__ __half g_Xh[(size_t)N_ROWS * I_FEAT];   // x, fp16

// ---------------- x -> fp16 ----------------
__global__ void tohalf_x_kernel(const float* __restrict__ x) {
    size_t base = ((size_t)blockIdx.x * blockDim.x + threadIdx.x) * 4;
    float4 v = *reinterpret_cast<const float4*>(x + base);
    __half2 h0 = __floats2half2_rn(v.x, v.y);
    __half2 h1 = __floats2half2_rn(v.z, v.w);
    *reinterpret_cast<__half2*>(g_Xh + base)     = h0;
    *reinterpret_cast<__half2*>(g_Xh + base + 2) = h1;
}

// ---------------- dequantize W -> fp16 ----------------
__global__ void dequant_kernel(const int* __restrict__ idx,
                               const float* __restrict__ scales,
                               const float* __restrict__ bab) {
    size_t base = ((size_t)blockIdx.x * blockDim.x + threadIdx.x) * 4;
    int4 q = *reinterpret_cast<const int4*>(idx + base);
    size_t row = base >> 12;                 // / 4096
    int col = (int)(base & 4095);
    int blk = (int)(row << 4) + (col >> 8);  // row*16 + col/256
    float s = scales[blk] * (1.0f / 127.0f);
    float b = bab[blk];
    float w0 = (float)(q.x - 128) * s + b;
    float w1 = (float)(q.y - 128) * s + b;
    float w2 = (float)(q.z - 128) * s + b;
    float w3 = (float)(q.w - 128) * s + b;
    *reinterpret_cast<__half2*>(g_Wh + base)     = __floats2half2_rn(w0, w1);
    *reinterpret_cast<__half2*>(g_Wh + base + 2) = __floats2half2_rn(w2, w3);
}

// ---------------- GEMM helpers ----------------
__device__ __forceinline__ void cp16(uint32_t dst, const void* src) {
    asm volatile("cp.async.cg.shared.global [%0], [%1], 16;\n" :: "r"(dst), "l"(src));
}
__device__ __forceinline__ void ldsm4(uint32_t& r0, uint32_t& r1, uint32_t& r2, uint32_t& r3,
                                      uint32_t addr) {
    asm volatile("ldmatrix.sync.aligned.m8n8.x4.shared.b16 {%0,%1,%2,%3}, [%4];\n"
        : "=r"(r0), "=r"(r1), "=r"(r2), "=r"(r3) : "r"(addr));
}
__device__ __forceinline__ void mma16816(float* c, const uint32_t* a, const uint32_t* b) {
    asm volatile("mma.sync.aligned.m16n8k16.row.col.f32.f16.f16.f32 "
        "{%0,%1,%2,%3}, {%4,%5,%6,%7}, {%8,%9}, {%0,%1,%2,%3};\n"
        : "+f"(c[0]), "+f"(c[1]), "+f"(c[2]), "+f"(c[3])
        : "r"(a[0]), "r"(a[1]), "r"(a[2]), "r"(a[3]), "r"(b[0]), "r"(b[1]));
}

// ---------------- single fp16 GEMM: out = Xh @ Wh^T + bias ----------------
__global__ void __launch_bounds__(256, 1)
gemm_kernel(const float* __restrict__ bias, float* __restrict__ out) {
    extern __shared__ __align__(16) __half sm[];
    const uint32_t smbase = (uint32_t)__cvta_generic_to_shared(sm);
    constexpr int TSZ_A = BM * SSTRIDE;              // 5120 halves
    constexpr int TSZ_B = BN * SSTRIDE;              // 10240 halves
    constexpr int STG = TSZ_A + TSZ_B;               // per-stage halves (15360)

    const int m0 = (blockIdx.x & 31) * BM;           // m fastest -> W tiles shared via L2
    const int n0 = (blockIdx.x >> 5) * BN;
    const int tid = threadIdx.x;
    const int lane = tid & 31;
    const int wm = ((tid >> 5) & 1) * 64;            // 2 warps in m
    const int wn = (tid >> 6) * 64;                  // 4 warps in n, warp tile 64x64

    // ---- cp.async descriptors: thread covers row=tid>>2 (+64k), chunk tid&3
    const int rowa = tid >> 2;
    const int ch = tid & 3;
    const __half* pA = g_Xh + (size_t)(m0 + rowa) * I_FEAT + ch * 8;
    const __half* pB = g_Wh + (size_t)(n0 + rowa) * I_FEAT + ch * 8;
    const uint32_t dA = (uint32_t)(rowa * SSTRIDE + ch * 8) * 2;
    const uint32_t dB = (uint32_t)(TSZ_A + rowa * SSTRIDE + ch * 8) * 2;
    constexpr size_t RSTEP = (size_t)64 * I_FEAT;
    constexpr uint32_t DSTEP = (uint32_t)(64 * SSTRIDE) * 2;

    float acc[4][8][4];
#pragma unroll
    for (int i = 0; i < 4; ++i)
#pragma unroll
        for (int j = 0; j < 8; ++j)
#pragma unroll
            for (int k = 0; k < 4; ++k) acc[i][j][k] = 0.0f;

    auto load_stage = [&](uint32_t sb, int kt) {
        const __half* a = pA + (size_t)kt * BK;
        const __half* b = pB + (size_t)kt * BK;
#pragma unroll
        for (int i = 0; i < 2; ++i)
            cp16(sb + dA + i * DSTEP, a + i * RSTEP);
#pragma unroll
        for (int i = 0; i < 4; ++i)
            cp16(sb + dB + i * DSTEP, b + i * RSTEP);
    };

    // prologue: stage 0 <- k-tile 0
    load_stage(smbase, 0);
    asm volatile("cp.async.commit_group;\n");

    for (int kt = 0; kt < NKT; ++kt) {
        if (kt + 1 < NKT)
            load_stage(smbase + (uint32_t)((kt + 1) & 1) * (STG * 2), kt + 1);
        asm volatile("cp.async.commit_group;\n");
        asm volatile("cp.async.wait_group 1;\n");
        __syncthreads();

        const uint32_t sA = smbase + (uint32_t)(kt & 1) * (STG * 2);
        const uint32_t sB = sA + TSZ_A * 2;

#pragma unroll
        for (int ks = 0; ks < 2; ++ks) {
            uint32_t B[8][2];
#pragma unroll
            for (int j = 0; j < 4; ++j) {
                int brow = wn + j * 16 + (lane & 7) + ((lane >> 4) << 3);
                int bcol = ks * 16 + ((lane >> 3) & 1) * 8;
                uint32_t off = (uint32_t)(brow * SSTRIDE + bcol) * 2;
                ldsm4(B[j*2][0], B[j*2][1], B[j*2+1][0], B[j*2+1][1], sB + off);
            }
#pragma unroll
            for (int mi = 0; mi < 4; ++mi) {
                int arow = wm + mi * 16 + (lane & 15);
                int acol = ks * 16 + ((lane >> 4) << 3);
                uint32_t off = (uint32_t)(arow * SSTRIDE + acol) * 2;
                uint32_t a[4];
                ldsm4(a[0], a[1], a[2], a[3], sA + off);
#pragma unroll
                for (int ni = 0; ni < 8; ++ni)
                    mma16816(acc[mi][ni], a, B[ni]);
            }
        }
        __syncthreads();
    }

    // ---- epilogue: add bias, store fp32 ----
    const int g = lane >> 2;
    const int t4 = lane & 3;
    float2 bb[8];
#pragma unroll
    for (int ni = 0; ni < 8; ++ni) {
        int col = n0 + wn + ni * 8 + t4 * 2;
        bb[ni].x = __ldg(bias + col);
        bb[ni].y = __ldg(bias + col + 1);
    }
#pragma unroll
    for (int mi = 0; mi < 4; ++mi) {
        int row0 = m0 + wm + mi * 16 + g;
#pragma unroll
        for (int ni = 0; ni < 8; ++ni) {
            int col = n0 + wn + ni * 8 + t4 * 2;
            float2 v0 = { acc[mi][ni][0] + bb[ni].x, acc[mi][ni][1] + bb[ni].y };
            float2 v1 = { acc[mi][ni][2] + bb[ni].x, acc[mi][ni][3] + bb[ni].y };
            *reinterpret_cast<float2*>(out + (size_t)row0 * O_FEAT + col) = v0;
            *reinterpret_cast<float2*>(out + (size_t)(row0 + 8) * O_FEAT + col) = v1;
        }
    }
}

// ---------------- launch ----------------
extern "C" void kernel_launch(void* const* d_in, const int* in_sizes, int n_in,
                              void* d_out, int out_size) {
    const float* x    = (const float*)d_in[0];
    const int*   idx  = (const int*)d_in[1];
    const float* sc   = (const float*)d_in[2];
    const float* bab  = (const float*)d_in[3];
    const float* bias = (const float*)d_in[4];
    float* out = (float*)d_out;

    tohalf_x_kernel<<<(int)(((size_t)N_ROWS * I_FEAT) / 1024), 256>>>(x);
    dequant_kernel<<<(int)(((size_t)O_FEAT * I_FEAT) / 1024), 256>>>(idx, sc, bab);

    const int smem_bytes = 2 * (BM + BN) * SSTRIDE * 2;   // 61440
    cudaFuncSetAttribute(gemm_kernel, cudaFuncAttributeMaxDynamicSharedMemorySize, smem_bytes);
    gemm_kernel<<<(N_ROWS / BM) * (O_FEAT / BN), 256, smem_bytes>>>(bias, out);
}

// round 6
// speedup vs baseline: 4.4088x; 1.1760x over previous
#include <cuda_runtime.h>
#include <cuda_fp16.h>
#include <stdint.h>

#define I_FEAT 4096
#define O_FEAT 11008
#define N_ROWS 4096

#define BM 128
#define BN 128
#define BK 32
#define SSTRIDE 40                  // halves per smem row (32 + 8 pad)
#define NKT (I_FEAT / BK)           // 128 k-tiles
#define NSTG 3                      // pipeline stages

// ---------------- scratch (allocation-free: device globals) ----------------
__device__ __half g_Wh[(size_t)O_FEAT * I_FEAT];   // dequantized W, fp16
__device__ __half g_Xh[(size_t)N_ROWS * I_FEAT];   // x, fp16

// ---------------- x -> fp16 ----------------
__global__ void tohalf_x_kernel(const float* __restrict__ x) {
    size_t base = ((size_t)blockIdx.x * blockDim.x + threadIdx.x) * 4;
    float4 v = *reinterpret_cast<const float4*>(x + base);
    *reinterpret_cast<__half2*>(g_Xh + base)     = __floats2half2_rn(v.x, v.y);
    *reinterpret_cast<__half2*>(g_Xh + base + 2) = __floats2half2_rn(v.z, v.w);
}

// ---------------- dequantize W -> fp16 ----------------
__global__ void dequant_kernel(const int* __restrict__ idx,
                               const float* __restrict__ scales,
                               const float* __restrict__ bab) {
    size_t base = ((size_t)blockIdx.x * blockDim.x + threadIdx.x) * 4;
    int4 q = *reinterpret_cast<const int4*>(idx + base);
    size_t row = base >> 12;                 // / 4096
    int col = (int)(base & 4095);
    int blk = (int)(row << 4) + (col >> 8);  // row*16 + col/256
    float s = scales[blk] * (1.0f / 127.0f);
    float b = bab[blk];
    float w0 = (float)(q.x - 128) * s + b;
    float w1 = (float)(q.y - 128) * s + b;
    float w2 = (float)(q.z - 128) * s + b;
    float w3 = (float)(q.w - 128) * s + b;
    *reinterpret_cast<__half2*>(g_Wh + base)     = __floats2half2_rn(w0, w1);
    *reinterpret_cast<__half2*>(g_Wh + base + 2) = __floats2half2_rn(w2, w3);
}

// ---------------- GEMM helpers ----------------
__device__ __forceinline__ void cp16(uint32_t dst, const void* src) {
    asm volatile("cp.async.cg.shared.global [%0], [%1], 16;\n" :: "r"(dst), "l"(src));
}
__device__ __forceinline__ void ldsm4(uint32_t& r0, uint32_t& r1, uint32_t& r2, uint32_t& r3,
                                      uint32_t addr) {
    asm volatile("ldmatrix.sync.aligned.m8n8.x4.shared.b16 {%0,%1,%2,%3}, [%4];\n"
        : "=r"(r0), "=r"(r1), "=r"(r2), "=r"(r3) : "r"(addr));
}
__device__ __forceinline__ void mma16816(float* c, const uint32_t* a, const uint32_t* b) {
    asm volatile("mma.sync.aligned.m16n8k16.row.col.f32.f16.f16.f32 "
        "{%0,%1,%2,%3}, {%4,%5,%6,%7}, {%8,%9}, {%0,%1,%2,%3};\n"
        : "+f"(c[0]), "+f"(c[1]), "+f"(c[2]), "+f"(c[3])
        : "r"(a[0]), "r"(a[1]), "r"(a[2]), "r"(a[3]), "r"(b[0]), "r"(b[1]));
}

// ---------------- single fp16 GEMM, 3-stage pipeline, occ 2 ----------------
__global__ void __launch_bounds__(256, 2)
gemm_kernel(const float* __restrict__ bias, float* __restrict__ out) {
    extern __shared__ __align__(16) __half sm[];
    const uint32_t smbase = (uint32_t)__cvta_generic_to_shared(sm);
    constexpr int TSZ = BM * SSTRIDE;            // 5120 halves per tile
    constexpr int STG = 2 * TSZ;                 // per-stage halves (A+B)

    const int m0 = (blockIdx.x & 31) * BM;       // m fastest -> W tiles shared via L2
    const int n0 = (blockIdx.x >> 5) * BN;
    const int tid = threadIdx.x;
    const int lane = tid & 31;
    const int wm = ((tid >> 5) & 1) * 64;        // 2 warps in m
    const int wn = (tid >> 6) * 32;              // 4 warps in n, warp tile 64x32

    // ---- cp.async descriptors: 4 x 16B per thread per stage ----
    const int rowa = tid >> 2;
    const int ch = tid & 3;
    const __half* pA = g_Xh + (size_t)(m0 + rowa) * I_FEAT + ch * 8;
    const __half* pB = g_Wh + (size_t)(n0 + rowa) * I_FEAT + ch * 8;
    const uint32_t dA = (uint32_t)(rowa * SSTRIDE + ch * 8) * 2;
    const uint32_t dB = (uint32_t)(TSZ + rowa * SSTRIDE + ch * 8) * 2;
    constexpr size_t RSTEP = (size_t)64 * I_FEAT;
    constexpr uint32_t DSTEP = (uint32_t)(64 * SSTRIDE) * 2;

    auto load_stage = [&](int stg, int kt) {
        const uint32_t sb = smbase + (uint32_t)stg * (STG * 2);
        const __half* a = pA + (size_t)kt * BK;
        const __half* b = pB + (size_t)kt * BK;
        cp16(sb + dA, a);
        cp16(sb + dA + DSTEP, a + RSTEP);
        cp16(sb + dB, b);
        cp16(sb + dB + DSTEP, b + RSTEP);
    };

    float acc[4][4][4];
#pragma unroll
    for (int i = 0; i < 4; ++i)
#pragma unroll
        for (int j = 0; j < 4; ++j)
#pragma unroll
            for (int k = 0; k < 4; ++k) acc[i][j][k] = 0.0f;

    // prologue: stages 0..1 <- k-tiles 0..1
#pragma unroll
    for (int s = 0; s < NSTG - 1; ++s) {
        load_stage(s, s);
        asm volatile("cp.async.commit_group;\n");
    }

    int stg_w = NSTG - 1, stg_r = 0;
    for (int kt = 0; kt < NKT; ++kt) {
        if (kt + NSTG - 1 < NKT)
            load_stage(stg_w, kt + NSTG - 1);
        asm volatile("cp.async.commit_group;\n");
        asm volatile("cp.async.wait_group %0;\n" :: "n"(NSTG - 1));
        __syncthreads();                          // visibility: all threads' stage-kt data

        const uint32_t sA = smbase + (uint32_t)stg_r * (STG * 2);
        const uint32_t sB = sA + TSZ * 2;
        if (++stg_w == NSTG) stg_w = 0;
        if (++stg_r == NSTG) stg_r = 0;

#pragma unroll
        for (int ks = 0; ks < 2; ++ks) {
            uint32_t B[4][2];
#pragma unroll
            for (int j = 0; j < 2; ++j) {
                int brow = wn + j * 16 + (lane & 7) + ((lane >> 4) << 3);
                int bcol = ks * 16 + ((lane >> 3) & 1) * 8;
                uint32_t off = (uint32_t)(brow * SSTRIDE + bcol) * 2;
                ldsm4(B[j*2][0], B[j*2][1], B[j*2+1][0], B[j*2+1][1], sB + off);
            }
#pragma unroll
            for (int mi = 0; mi < 4; ++mi) {
                int arow = wm + mi * 16 + (lane & 15);
                int acol = ks * 16 + ((lane >> 4) << 3);
                uint32_t off = (uint32_t)(arow * SSTRIDE + acol) * 2;
                uint32_t a[4];
                ldsm4(a[0], a[1], a[2], a[3], sA + off);
#pragma unroll
                for (int ni = 0; ni < 4; ++ni)
                    mma16816(acc[mi][ni], a, B[ni]);
            }
        }
        __syncthreads();                          // WAR: next iter's loads overwrite safely
    }

    // ---- epilogue: add bias, store fp32 ----
    const int g = lane >> 2;
    const int t4 = lane & 3;
    float2 bb[4];
#pragma unroll
    for (int ni = 0; ni < 4; ++ni) {
        int col = n0 + wn + ni * 8 + t4 * 2;
        bb[ni].x = __ldg(bias + col);
        bb[ni].y = __ldg(bias + col + 1);
    }
#pragma unroll
    for (int mi = 0; mi < 4; ++mi) {
        int row0 = m0 + wm + mi * 16 + g;
#pragma unroll
        for (int ni = 0; ni < 4; ++ni) {
            int col = n0 + wn + ni * 8 + t4 * 2;
            float2 v0 = { acc[mi][ni][0] + bb[ni].x, acc[mi][ni][1] + bb[ni].y };
            float2 v1 = { acc[mi][ni][2] + bb[ni].x, acc[mi][ni][3] + bb[ni].y };
            *reinterpret_cast<float2*>(out + (size_t)row0 * O_FEAT + col) = v0;
            *reinterpret_cast<float2*>(out + (size_t)(row0 + 8) * O_FEAT + col) = v1;
        }
    }
}

// ---------------- launch ----------------
extern "C" void kernel_launch(void* const* d_in, const int* in_sizes, int n_in,
                              void* d_out, int out_size) {
    const float* x    = (const float*)d_in[0];
    const int*   idx  = (const int*)d_in[1];
    const float* sc   = (const float*)d_in[2];
    const float* bab  = (const float*)d_in[3];
    const float* bias = (const float*)d_in[4];
    float* out = (float*)d_out;

    tohalf_x_kernel<<<(int)(((size_t)N_ROWS * I_FEAT) / 1024), 256>>>(x);
    dequant_kernel<<<(int)(((size_t)O_FEAT * I_FEAT) / 1024), 256>>>(idx, sc, bab);

    const int smem_bytes = NSTG * 2 * BM * SSTRIDE * 2;   // 61440
    cudaFuncSetAttribute(gemm_kernel, cudaFuncAttributeMaxDynamicSharedMemorySize, smem_bytes);
    gemm_kernel<<<(N_ROWS / BM) * (O_FEAT / BN), 256, smem_bytes>>>(bias, out);
}

// round 7
// speedup vs baseline: 5.1844x; 1.1759x over previous
#include <cuda_runtime.h>
#include <cuda_fp16.h>
#include <stdint.h>

#define I_FEAT 4096
#define O_FEAT 11008
#define N_ROWS 4096

#define BM 128
#define BN 128
#define BK 32
#define SSTRIDE 40                  // halves per smem row (32 + 8 pad)
#define NKT (I_FEAT / BK)           // 128 k-tiles
#define NSTG 4                      // pipeline stages

// ---------------- scratch (allocation-free: device globals) ----------------
__device__ __half g_Wh[(size_t)O_FEAT * I_FEAT];   // dequantized W, fp16
__device__ __half g_Xh[(size_t)N_ROWS * I_FEAT];   // x, fp16

// ---------------- x -> fp16 ----------------
__global__ void tohalf_x_kernel(const float* __restrict__ x) {
    size_t base = ((size_t)blockIdx.x * blockDim.x + threadIdx.x) * 4;
    float4 v = *reinterpret_cast<const float4*>(x + base);
    *reinterpret_cast<__half2*>(g_Xh + base)     = __floats2half2_rn(v.x, v.y);
    *reinterpret_cast<__half2*>(g_Xh + base + 2) = __floats2half2_rn(v.z, v.w);
}

// ---------------- dequantize W -> fp16 ----------------
__global__ void dequant_kernel(const int* __restrict__ idx,
                               const float* __restrict__ scales,
                               const float* __restrict__ bab) {
    size_t base = ((size_t)blockIdx.x * blockDim.x + threadIdx.x) * 4;
    int4 q = *reinterpret_cast<const int4*>(idx + base);
    size_t row = base >> 12;                 // / 4096
    int col = (int)(base & 4095);
    int blk = (int)(row << 4) + (col >> 8);  // row*16 + col/256
    float s = scales[blk] * (1.0f / 127.0f);
    float b = bab[blk];
    float w0 = (float)(q.x - 128) * s + b;
    float w1 = (float)(q.y - 128) * s + b;
    float w2 = (float)(q.z - 128) * s + b;
    float w3 = (float)(q.w - 128) * s + b;
    *reinterpret_cast<__half2*>(g_Wh + base)     = __floats2half2_rn(w0, w1);
    *reinterpret_cast<__half2*>(g_Wh + base + 2) = __floats2half2_rn(w2, w3);
}

// ---------------- GEMM helpers ----------------
__device__ __forceinline__ void cp16(uint32_t dst, const void* src) {
    asm volatile("cp.async.cg.shared.global [%0], [%1], 16;\n" :: "r"(dst), "l"(src));
}
__device__ __forceinline__ void ldsm4(uint32_t& r0, uint32_t& r1, uint32_t& r2, uint32_t& r3,
                                      uint32_t addr) {
    asm volatile("ldmatrix.sync.aligned.m8n8.x4.shared.b16 {%0,%1,%2,%3}, [%4];\n"
        : "=r"(r0), "=r"(r1), "=r"(r2), "=r"(r3) : "r"(addr));
}
__device__ __forceinline__ void mma16816(float* c, const uint32_t* a, const uint32_t* b) {
    asm volatile("mma.sync.aligned.m16n8k16.row.col.f32.f16.f16.f32 "
        "{%0,%1,%2,%3}, {%4,%5,%6,%7}, {%8,%9}, {%0,%1,%2,%3};\n"
        : "+f"(c[0]), "+f"(c[1]), "+f"(c[2]), "+f"(c[3])
        : "r"(a[0]), "r"(a[1]), "r"(a[2]), "r"(a[3]), "r"(b[0]), "r"(b[1]));
}

// ---------------- single fp16 GEMM, 4-stage, ONE barrier per iter ----------------
__global__ void __launch_bounds__(256, 2)
gemm_kernel(const float* __restrict__ bias, float* __restrict__ out) {
    extern __shared__ __align__(16) __half sm[];
    const uint32_t smbase = (uint32_t)__cvta_generic_to_shared(sm);
    constexpr int TSZ = BM * SSTRIDE;            // 5120 halves per tile
    constexpr int STG = 2 * TSZ;                 // per-stage halves (A+B)

    const int m0 = (blockIdx.x & 31) * BM;       // m fastest -> W tiles shared via L2
    const int n0 = (blockIdx.x >> 5) * BN;
    const int tid = threadIdx.x;
    const int lane = tid & 31;
    const int wm = ((tid >> 5) & 1) * 64;        // 2 warps in m
    const int wn = (tid >> 6) * 32;              // 4 warps in n, warp tile 64x32

    // ---- cp.async descriptors: 4 x 16B per thread per stage ----
    const int rowa = tid >> 2;
    const int ch = tid & 3;
    const __half* pA = g_Xh + (size_t)(m0 + rowa) * I_FEAT + ch * 8;
    const __half* pB = g_Wh + (size_t)(n0 + rowa) * I_FEAT + ch * 8;
    const uint32_t dA = (uint32_t)(rowa * SSTRIDE + ch * 8) * 2;
    const uint32_t dB = (uint32_t)(TSZ + rowa * SSTRIDE + ch * 8) * 2;
    constexpr size_t RSTEP = (size_t)64 * I_FEAT;
    constexpr uint32_t DSTEP = (uint32_t)(64 * SSTRIDE) * 2;

    auto load_stage = [&](int stg, int kt) {
        const uint32_t sb = smbase + (uint32_t)stg * (STG * 2);
        const __half* a = pA + (size_t)kt * BK;
        const __half* b = pB + (size_t)kt * BK;
        cp16(sb + dA, a);
        cp16(sb + dA + DSTEP, a + RSTEP);
        cp16(sb + dB, b);
        cp16(sb + dB + DSTEP, b + RSTEP);
    };

    float acc[4][4][4];
#pragma unroll
    for (int i = 0; i < 4; ++i)
#pragma unroll
        for (int j = 0; j < 4; ++j)
#pragma unroll
            for (int k = 0; k < 4; ++k) acc[i][j][k] = 0.0f;

    // prologue: stages 0..2 <- k-tiles 0..2
#pragma unroll
    for (int s = 0; s < NSTG - 1; ++s) {
        load_stage(s, s);
        asm volatile("cp.async.commit_group;\n");
    }

    int stg_w = NSTG - 1, stg_r = 0;
    for (int kt = 0; kt < NKT; ++kt) {
        asm volatile("cp.async.wait_group %0;\n" :: "n"(NSTG - 2));
        __syncthreads();   // stage kt visible to all; all warps done reading stage kt-1

        const uint32_t sA = smbase + (uint32_t)stg_r * (STG * 2);
        const uint32_t sB = sA + TSZ * 2;

        // ---- ks = 0 ----
        {
            uint32_t B[4][2];
#pragma unroll
            for (int j = 0; j < 2; ++j) {
                int brow = wn + j * 16 + (lane & 7) + ((lane >> 4) << 3);
                int bcol = ((lane >> 3) & 1) * 8;
                uint32_t off = (uint32_t)(brow * SSTRIDE + bcol) * 2;
                ldsm4(B[j*2][0], B[j*2][1], B[j*2+1][0], B[j*2+1][1], sB + off);
            }
#pragma unroll
            for (int mi = 0; mi < 4; ++mi) {
                int arow = wm + mi * 16 + (lane & 15);
                int acol = ((lane >> 4) << 3);
                uint32_t off = (uint32_t)(arow * SSTRIDE + acol) * 2;
                uint32_t a[4];
                ldsm4(a[0], a[1], a[2], a[3], sA + off);
#pragma unroll
                for (int ni = 0; ni < 4; ++ni)
                    mma16816(acc[mi][ni], a, B[ni]);
            }
        }

        // ---- prefetch stage kt+NSTG-1 (overwrites buffer kt-1: safe post-barrier) ----
        if (kt + NSTG - 1 < NKT)
            load_stage(stg_w, kt + NSTG - 1);
        asm volatile("cp.async.commit_group;\n");

        // ---- ks = 1 ----
        {
            uint32_t B[4][2];
#pragma unroll
            for (int j = 0; j < 2; ++j) {
                int brow = wn + j * 16 + (lane & 7) + ((lane >> 4) << 3);
                int bcol = 16 + ((lane >> 3) & 1) * 8;
                uint32_t off = (uint32_t)(brow * SSTRIDE + bcol) * 2;
                ldsm4(B[j*2][0], B[j*2][1], B[j*2+1][0], B[j*2+1][1], sB + off);
            }
#pragma unroll
            for (int mi = 0; mi < 4; ++mi) {
                int arow = wm + mi * 16 + (lane & 15);
                int acol = 16 + ((lane >> 4) << 3);
                uint32_t off = (uint32_t)(arow * SSTRIDE + acol) * 2;
                uint32_t a[4];
                ldsm4(a[0], a[1], a[2], a[3], sA + off);
#pragma unroll
                for (int ni = 0; ni < 4; ++ni)
                    mma16816(acc[mi][ni], a, B[ni]);
            }
        }

        if (++stg_w == NSTG) stg_w = 0;
        if (++stg_r == NSTG) stg_r = 0;
    }

    // ---- epilogue: add bias, store fp32 ----
    const int g = lane >> 2;
    const int t4 = lane & 3;
    float2 bb[4];
#pragma unroll
    for (int ni = 0; ni < 4; ++ni) {
        int col = n0 + wn + ni * 8 + t4 * 2;
        bb[ni].x = __ldg(bias + col);
        bb[ni].y = __ldg(bias + col + 1);
    }
#pragma unroll
    for (int mi = 0; mi < 4; ++mi) {
        int row0 = m0 + wm + mi * 16 + g;
#pragma unroll
        for (int ni = 0; ni < 4; ++ni) {
            int col = n0 + wn + ni * 8 + t4 * 2;
            float2 v0 = { acc[mi][ni][0] + bb[ni].x, acc[mi][ni][1] + bb[ni].y };
            float2 v1 = { acc[mi][ni][2] + bb[ni].x, acc[mi][ni][3] + bb[ni].y };
            *reinterpret_cast<float2*>(out + (size_t)row0 * O_FEAT + col) = v0;
            *reinterpret_cast<float2*>(out + (size_t)(row0 + 8) * O_FEAT + col) = v1;
        }
    }
}

// ---------------- launch ----------------
extern "C" void kernel_launch(void* const* d_in, const int* in_sizes, int n_in,
                              void* d_out, int out_size) {
    const float* x    = (const float*)d_in[0];
    const int*   idx  = (const int*)d_in[1];
    const float* sc   = (const float*)d_in[2];
    const float* bab  = (const float*)d_in[3];
    const float* bias = (const float*)d_in[4];
    float* out = (float*)d_out;

    tohalf_x_kernel<<<(int)(((size_t)N_ROWS * I_FEAT) / 1024), 256>>>(x);
    dequant_kernel<<<(int)(((size_t)O_FEAT * I_FEAT) / 1024), 256>>>(idx, sc, bab);

    const int smem_bytes = NSTG * 2 * BM * SSTRIDE * 2;   // 81920
    cudaFuncSetAttribute(gemm_kernel, cudaFuncAttributeMaxDynamicSharedMemorySize, smem_bytes);
    gemm_kernel<<<(N_ROWS / BM) * (O_FEAT / BN), 256, smem_bytes>>>(bias, out);
}

// round 9
// speedup vs baseline: 5.6492x; 1.0897x over previous
#include <cuda_runtime.h>
#include <cuda_fp16.h>
#include <stdint.h>

#define I_FEAT 4096
#define O_FEAT 11008
#define N_ROWS 4096

#define BM 128
#define BN 128
#define BK 32
#define SSTRIDE 40                  // halves per smem row (32 + 8 pad)
#define NKT (I_FEAT / BK)           // 128 k-tiles
#define NSTG 4                      // pipeline stages

// ---------------- scratch (allocation-free: device globals) ----------------
__device__ __half g_Wh[(size_t)O_FEAT * I_FEAT];   // dequantized W, fp16
__device__ __half g_Xh[(size_t)N_ROWS * I_FEAT];   // x, fp16

__device__ __forceinline__ uint32_t h2u(__half2 h) {
    union { __half2 h; uint32_t u; } c; c.h = h; return c.u;
}

// ---------------- x -> fp16 (8 elem/thread, one 16B store) ----------------
__global__ void tohalf_x_kernel(const float* __restrict__ x) {
    size_t base = ((size_t)blockIdx.x * blockDim.x + threadIdx.x) * 8;
    float4 v0 = *reinterpret_cast<const float4*>(x + base);
    float4 v1 = *reinterpret_cast<const float4*>(x + base + 4);
    uint4 o;
    o.x = h2u(__floats2half2_rn(v0.x, v0.y));
    o.y = h2u(__floats2half2_rn(v0.z, v0.w));
    o.z = h2u(__floats2half2_rn(v1.x, v1.y));
    o.w = h2u(__floats2half2_rn(v1.z, v1.w));
    *reinterpret_cast<uint4*>(g_Xh + base) = o;
}

// ---------------- dequantize W -> fp16 (8 elem/thread, one 16B store) -------
__global__ void dequant_kernel(const int* __restrict__ idx,
                               const float* __restrict__ scales,
                               const float* __restrict__ bab) {
    size_t base = ((size_t)blockIdx.x * blockDim.x + threadIdx.x) * 8;
    int4 q0 = *reinterpret_cast<const int4*>(idx + base);
    int4 q1 = *reinterpret_cast<const int4*>(idx + base + 4);
    size_t row = base >> 12;                 // / 4096
    int col = (int)(base & 4095);
    int blk = (int)(row << 4) + (col >> 8);  // 8 elems never cross a 256-block
    float s = scales[blk] * (1.0f / 127.0f);
    float b = bab[blk];
    float w0 = (float)(q0.x - 128) * s + b;
    float w1 = (float)(q0.y - 128) * s + b;
    float w2 = (float)(q0.z - 128) * s + b;
    float w3 = (float)(q0.w - 128) * s + b;
    float w4 = (float)(q1.x - 128) * s + b;
    float w5 = (float)(q1.y - 128) * s + b;
    float w6 = (float)(q1.z - 128) * s + b;
    float w7 = (float)(q1.w - 128) * s + b;
    uint4 o;
    o.x = h2u(__floats2half2_rn(w0, w1));
    o.y = h2u(__floats2half2_rn(w2, w3));
    o.z = h2u(__floats2half2_rn(w4, w5));
    o.w = h2u(__floats2half2_rn(w6, w7));
    *reinterpret_cast<uint4*>(g_Wh + base) = o;
}

// ---------------- GEMM helpers ----------------
__device__ __forceinline__ void cp16(uint32_t dst, const void* src) {
    asm volatile("cp.async.cg.shared.global [%0], [%1], 16;\n" :: "r"(dst), "l"(src));
}
__device__ __forceinline__ void ldsm4(uint32_t& r0, uint32_t& r1, uint32_t& r2, uint32_t& r3,
                                      uint32_t addr) {
    asm volatile("ldmatrix.sync.aligned.m8n8.x4.shared.b16 {%0,%1,%2,%3}, [%4];\n"
        : "=r"(r0), "=r"(r1), "=r"(r2), "=r"(r3) : "r"(addr));
}
__device__ __forceinline__ void mma16816(float* c, const uint32_t* a, const uint32_t* b) {
    asm volatile("mma.sync.aligned.m16n8k16.row.col.f32.f16.f16.f32 "
        "{%0,%1,%2,%3}, {%4,%5,%6,%7}, {%8,%9}, {%0,%1,%2,%3};\n"
        : "+f"(c[0]), "+f"(c[1]), "+f"(c[2]), "+f"(c[3])
        : "r"(a[0]), "r"(a[1]), "r"(a[2]), "r"(a[3]), "r"(b[0]), "r"(b[1]));
}

// ---------------- single fp16 GEMM, 4-stage, one barrier/iter ----------------
__global__ void __launch_bounds__(256, 2)
gemm_kernel(const float* __restrict__ bias, float* __restrict__ out) {
    extern __shared__ __align__(16) __half sm[];
    const uint32_t smbase = (uint32_t)__cvta_generic_to_shared(sm);
    constexpr int TSZ = BM * SSTRIDE;            // 5120 halves per tile
    constexpr uint32_t STGB = 2u * TSZ * 2u;     // stage bytes (A+B)

    const int m0 = (blockIdx.x & 31) * BM;       // m fastest -> W tiles shared via L2
    const int n0 = (blockIdx.x >> 5) * BN;
    const int tid = threadIdx.x;
    const int lane = tid & 31;
    const int wm = ((tid >> 5) & 1) * 64;        // 2 warps in m
    const int wn = (tid >> 6) * 32;              // 4 warps in n, warp tile 64x32

    // ---- cp.async descriptors: 4 x 16B per thread per stage ----
    const int rowa = tid >> 2;
    const int ch = tid & 3;
    const __half* pA = g_Xh + (size_t)(m0 + rowa) * I_FEAT + ch * 8;
    const __half* pB = g_Wh + (size_t)(n0 + rowa) * I_FEAT + ch * 8;
    const uint32_t dA = (uint32_t)(rowa * SSTRIDE + ch * 8) * 2;
    const uint32_t dB = (uint32_t)(TSZ + rowa * SSTRIDE + ch * 8) * 2;
    constexpr size_t RSTEP = (size_t)64 * I_FEAT;
    constexpr uint32_t DSTEP = (uint32_t)(64 * SSTRIDE) * 2;

    auto load_stage = [&](int stg, int kt) {
        const uint32_t sb = smbase + (uint32_t)stg * STGB;
        const __half* a = pA + (size_t)kt * BK;
        const __half* b = pB + (size_t)kt * BK;
        cp16(sb + dA, a);
        cp16(sb + dA + DSTEP, a + RSTEP);
        cp16(sb + dB, b);
        cp16(sb + dB + DSTEP, b + RSTEP);
    };

    // ---- hoisted ldsm offsets (relative to stage base) ----
    uint32_t offB[2][2], offA[2][4];   // [ks][j], [ks][mi]
#pragma unroll
    for (int ks = 0; ks < 2; ++ks) {
#pragma unroll
        for (int j = 0; j < 2; ++j) {
            int brow = wn + j * 16 + (lane & 7) + ((lane >> 4) << 3);
            int bcol = ks * 16 + ((lane >> 3) & 1) * 8;
            offB[ks][j] = (uint32_t)(TSZ + brow * SSTRIDE + bcol) * 2;
        }
#pragma unroll
        for (int mi = 0; mi < 4; ++mi) {
            int arow = wm + mi * 16 + (lane & 15);
            int acol = ks * 16 + ((lane >> 4) << 3);
            offA[ks][mi] = (uint32_t)(arow * SSTRIDE + acol) * 2;
        }
    }

    float acc[4][4][4];
#pragma unroll
    for (int i = 0; i < 4; ++i)
#pragma unroll
        for (int j = 0; j < 4; ++j)
#pragma unroll
            for (int k = 0; k < 4; ++k) acc[i][j][k] = 0.0f;

    // prologue: stages 0..2 <- k-tiles 0..2
#pragma unroll
    for (int s = 0; s < NSTG - 1; ++s) {
        load_stage(s, s);
        asm volatile("cp.async.commit_group;\n");
    }

#pragma unroll 4
    for (int kt = 0; kt < NKT; ++kt) {
        asm volatile("cp.async.wait_group %0;\n" :: "n"(NSTG - 2));
        __syncthreads();   // stage kt visible; all warps done reading stage kt-1

        const uint32_t sbase = smbase + (uint32_t)(kt & (NSTG - 1)) * STGB;

        // ---- ks = 0 ----
        {
            uint32_t B[4][2];
            ldsm4(B[0][0], B[0][1], B[1][0], B[1][1], sbase + offB[0][0]);
            ldsm4(B[2][0], B[2][1], B[3][0], B[3][1], sbase + offB[0][1]);
#pragma unroll
            for (int mi = 0; mi < 4; ++mi) {
                uint32_t a[4];
                ldsm4(a[0], a[1], a[2], a[3], sbase + offA[0][mi]);
#pragma unroll
                for (int ni = 0; ni < 4; ++ni)
                    mma16816(acc[mi][ni], a, B[ni]);
            }
        }

        // ---- prefetch stage kt+3 (overwrites buffer kt-1: safe post-barrier) ----
        if (kt + NSTG - 1 < NKT)
            load_stage((kt + NSTG - 1) & (NSTG - 1), kt + NSTG - 1);
        asm volatile("cp.async.commit_group;\n");

        // ---- ks = 1 ----
        {
            uint32_t B[4][2];
            ldsm4(B[0][0], B[0][1], B[1][0], B[1][1], sbase + offB[1][0]);
            ldsm4(B[2][0], B[2][1], B[3][0], B[3][1], sbase + offB[1][1]);
#pragma unroll
            for (int mi = 0; mi < 4; ++mi) {
                uint32_t a[4];
                ldsm4(a[0], a[1], a[2], a[3], sbase + offA[1][mi]);
#pragma unroll
                for (int ni = 0; ni < 4; ++ni)
                    mma16816(acc[mi][ni], a, B[ni]);
            }
        }
    }

    // ---- epilogue: add bias, store fp32 ----
    const int g = lane >> 2;
    const int t4 = lane & 3;
    float2 bb[4];
#pragma unroll
    for (int ni = 0; ni < 4; ++ni) {
        int col = n0 + wn + ni * 8 + t4 * 2;
        bb[ni].x = __ldg(bias + col);
        bb[ni].y = __ldg(bias + col + 1);
    }
#pragma unroll
    for (int mi = 0; mi < 4; ++mi) {
        int row0 = m0 + wm + mi * 16 + g;
#pragma unroll
        for (int ni = 0; ni < 4; ++ni) {
            int col = n0 + wn + ni * 8 + t4 * 2;
            float2 v0 = { acc[mi][ni][0] + bb[ni].x, acc[mi][ni][1] + bb[ni].y };
            float2 v1 = { acc[mi][ni][2] + bb[ni].x, acc[mi][ni][3] + bb[ni].y };
            *reinterpret_cast<float2*>(out + (size_t)row0 * O_FEAT + col) = v0;
            *reinterpret_cast<float2*>(out + (size_t)(row0 + 8) * O_FEAT + col) = v1;
        }
    }
}

// ---------------- launch ----------------
extern "C" void kernel_launch(void* const* d_in, const int* in_sizes, int n_in,
                              void* d_out, int out_size) {
    const float* x    = (const float*)d_in[0];
    const int*   idx  = (const int*)d_in[1];
    const float* sc   = (const float*)d_in[2];
    const float* bab  = (const float*)d_in[3];
    const float* bias = (const float*)d_in[4];
    float* out = (float*)d_out;

    tohalf_x_kernel<<<(int)(((size_t)N_ROWS * I_FEAT) / (256 * 8)), 256>>>(x);
    dequant_kernel<<<(int)(((size_t)O_FEAT * I_FEAT) / (256 * 8)), 256>>>(idx, sc, bab);

    const int smem_bytes = NSTG * 2 * BM * SSTRIDE * 2;   // 81920
    cudaFuncSetAttribute(gemm_kernel, cudaFuncAttributeMaxDynamicSharedMemorySize, smem_bytes);
    gemm_kernel<<<(N_ROWS / BM) * (O_FEAT / BN), 256, smem_bytes>>>(bias, out);
}